// round 9
// baseline (speedup 1.0000x reference)
#include <cuda_runtime.h>

#define FULLMASK 0xffffffffu

// ---------------------------------------------------------------------------
// Precomputed per-ring tables (row-independent):
//   g_cs[r][i][lane] = (cos, sin) of angle at k = 32*lane + 31 - i
//                      (lane 0, i==31 holds (c0, s0) for the wrap epilogue)
//   g_cp[r][i][lane] = c_k * P(i),  P(i) = prod_{i'<i} (-s_{k(i')})  (fixup coeff)
//   g_A [r][lane]    = full within-lane product of (-s)
// Lane-minor layout -> conflict-free LDS.
// ---------------------------------------------------------------------------
__device__ float2 g_cs[8][32][32];
__device__ float  g_cp[8][32][32];
__device__ float  g_A[8][32];

// ---------------------------------------------------------------------------
// Table precompute: one thread per (ring, lane). Trivial cost.
// ---------------------------------------------------------------------------
__global__ void precompute_tables(const float* __restrict__ ae,
                                  const float* __restrict__ ad) {
    int t = threadIdx.x;
    if (t >= 256) return;
    int r = t >> 5, lane = t & 31;
    const float* ang = (r < 4) ? (ae + r * 1024) : (ad + (r - 4) * 1024);
    float P = 1.0f;
    for (int i = 0; i < 32; i++) {
        int k = lane * 32 + 31 - i;
        float a = ang[k];
        float c = cosf(a), s = sinf(a);
        g_cs[r][i][lane] = make_float2(c, s);
        if (lane == 0 && i == 31) {
            g_cp[r][i][lane] = 0.0f;     // k==0 handled by wrap epilogue
        } else {
            g_cp[r][i][lane] = c * P;
            P *= -s;
        }
    }
    g_A[r][lane] = P;
}

// ---------------------------------------------------------------------------
// One ring applied to a warp's single row held in registers (scalar f32).
// Lane l owns columns [32l, 32l+32).
//   Main pass (descending k): y[k+1] = c*v + s*x_k ; v' = c*x_k - s*v
//   Then a 5-level affine suffix scan over lanes delivers the true incoming
//   carry V, and one FMA per element applies the row-independent fixup.
// ---------------------------------------------------------------------------
static __device__ __forceinline__ void apply_ring(
    float (&d)[32], int lane,
    const float2* __restrict__ cs,    // &s_cs[r][0][lane], stride 32 float2
    const float*  __restrict__ cp,    // &s_cp[r][0][lane], stride 32 float
    float Ain)
{
    float x0 = __shfl_sync(FULLMASK, d[0], 0);    // x[0] of the row

    float v   = 0.0f;                             // zero-init carry
    float bnd = 0.0f;                             // boundary output (slot 32l+32)

    #pragma unroll
    for (int i = 0; i < 31; i++) {
        float2 csv = cs[i * 32];
        float xk = d[31 - i];
        float sx = csv.y * xk;
        float sv = csv.y * v;
        float y0 = fmaf(csv.x, v, sx);            // c*v + s*x
        if (i == 0) bnd = y0; else d[32 - i] = y0;
        v = fmaf(csv.x, xk, -sv);                 // c*x - s*v
    }
    float2 cs31 = cs[31 * 32];
    float c0 = cs31.x, s0 = cs31.y;               // meaningful only for lane 0
    if (lane != 0) {                              // i == 31 chain step (k = 32*lane)
        float xk = d[0];
        float sx = cs31.y * xk;
        float sv = cs31.y * v;
        d[1] = fmaf(cs31.x, v, sx);
        v = fmaf(cs31.x, xk, -sv);
    }

    // Suffix scan of affine maps F_l(v) = A_l v + B_l over lanes (high -> low).
    float A = Ain, Aown = Ain;
    float q = v;
    float B = v;
    #pragma unroll
    for (int dd = 1; dd < 32; dd <<= 1) {
        float Ao = __shfl_down_sync(FULLMASK, A, dd);
        float Bo = __shfl_down_sync(FULLMASK, B, dd);
        float Bn = fmaf(A, Bo, B);
        float An = A * Ao;
        bool ok = (lane + dd < 32);               // predicated, no branch
        B = ok ? Bn : B;
        A = ok ? An : A;
    }
    float SA = __shfl_down_sync(FULLMASK, A, 1);
    float SB = __shfl_down_sync(FULLMASK, B, 1);
    float V = (lane == 31) ? x0 : fmaf(SA, x0, SB);

    // Fixups: y = y0 + CP * V  (CP row-independent)
    bnd = fmaf(cp[0], V, bnd);
    #pragma unroll
    for (int i = 1; i < 32; i++) {
        d[32 - i] = fmaf(cp[i * 32], V, d[32 - i]);
    }

    // Boundary pass: lane l's top output is lane l+1's lowest slot.
    // Lane 31's boundary p = s_{n-1} x_{n-1} + c_{n-1} x_0 feeds lane 0's wrap.
    float p2  = __shfl_sync(FULLMASK, bnd, 31);
    float rec = __shfl_up_sync(FULLMASK, bnd, 1);
    if (lane > 0) {
        d[0] = rec;
    } else {
        float vf = fmaf(Aown, V, q);              // carry_1
        d[0] = fmaf(-s0, vf, c0 * p2);            // y0 = c0 p - s0 carry1
        d[1] = fmaf(c0,  vf, s0 * p2);            // y1 = s0 p + c0 carry1
    }
}

// ---------------------------------------------------------------------------
// Fused kernel, 512 threads = 16 warps, ONE ROW PER WARP (scalar f32 state:
// d[32] = 32 regs -> ~100 regs total, fits the 128-reg cap of (512,1) with
// no spill). 16 warps/SM = 4/SMSP doubles latency-hiding vs the previous
// 8-warp/SM configs that were stuck at issue=18%.
// ---------------------------------------------------------------------------
extern "C" __global__ void __launch_bounds__(512, 1)
enc_dec_kernel(const float* __restrict__ x,
               const float* __restrict__ hw,
               const float* __restrict__ hs,
               float* __restrict__ out, int B)
{
    extern __shared__ unsigned char smem_raw[];
    float2* s_cs = (float2*)smem_raw;                         // 64 KB
    float*  s_cp = (float*)(smem_raw + 65536);                // 32 KB
    float*  s_A  = (float*)(smem_raw + 65536 + 32768);        // 1 KB
    {
        const float4* g1 = (const float4*)(const void*)g_cs;
        float4* s1 = (float4*)(void*)smem_raw;
        for (int i = threadIdx.x; i < 4096; i += 512) s1[i] = g1[i];
        const float4* g2 = (const float4*)(const void*)g_cp;
        float4* s2 = (float4*)(void*)(smem_raw + 65536);
        for (int i = threadIdx.x; i < 2048; i += 512) s2[i] = g2[i];
        const float4* g3 = (const float4*)(const void*)g_A;
        float4* s3 = (float4*)(void*)(smem_raw + 65536 + 32768);
        for (int i = threadIdx.x; i < 64; i += 512) s3[i] = g3[i];
    }
    __syncthreads();

    int warp = threadIdx.x >> 5;
    int lane = threadIdx.x & 31;

    long long row = (long long)blockIdx.x * 16 + warp;
    const float* pA = x + row * 1024 + lane * 32;

    // Each lane owns one 128B line (streaming reads, fully consumed).
    float d[32];
    #pragma unroll
    for (int t = 0; t < 8; t++) {
        float4 a = __ldcs((const float4*)(pA + 4 * t));
        d[4 * t + 0] = a.x;
        d[4 * t + 1] = a.y;
        d[4 * t + 2] = a.z;
        d[4 * t + 3] = a.w;
    }

    #pragma unroll 1
    for (int r = 0; r < 4; r++) {
        apply_ring(d, lane, s_cs + r * 1024 + lane, s_cp + r * 1024 + lane,
                   s_A[r * 32 + lane]);
    }

    // Bottleneck blend: (1-w)*b + w*h, w = sigmoid(hidden_weight[0])
    float hwv = __ldg(hw);
    float w = 1.0f / (1.0f + expf(-hwv));
    float iw = 1.0f - w;
    const float* ph = hs + lane * 32;
    float* ob = out + row * 1024 + lane * 32;
    float* oo = out + (long long)B * 1024 + row * 1024 + lane * 32;

    #pragma unroll
    for (int t = 0; t < 8; t++) {
        float4 h4 = *(const float4*)(ph + 4 * t);
        d[4 * t + 0] = fmaf(iw, d[4 * t + 0], w * h4.x);
        d[4 * t + 1] = fmaf(iw, d[4 * t + 1], w * h4.y);
        d[4 * t + 2] = fmaf(iw, d[4 * t + 2], w * h4.z);
        d[4 * t + 3] = fmaf(iw, d[4 * t + 3], w * h4.w);
        float4 o4 = make_float4(d[4 * t + 0], d[4 * t + 1],
                                d[4 * t + 2], d[4 * t + 3]);
        __stcs((float4*)(ob + 4 * t), o4);
    }

    #pragma unroll 1
    for (int r = 4; r < 8; r++) {
        apply_ring(d, lane, s_cs + r * 1024 + lane, s_cp + r * 1024 + lane,
                   s_A[r * 32 + lane]);
    }

    #pragma unroll
    for (int t = 0; t < 8; t++) {
        float4 o4 = make_float4(d[4 * t + 0], d[4 * t + 1],
                                d[4 * t + 2], d[4 * t + 3]);
        __stcs((float4*)(oo + 4 * t), o4);
    }
}

// ---------------------------------------------------------------------------
extern "C" void kernel_launch(void* const* d_in, const int* in_sizes, int n_in,
                              void* d_out, int out_size) {
    const float* x  = (const float*)d_in[0];
    const float* ae = (const float*)d_in[1];
    const float* ad = (const float*)d_in[2];
    const float* hw = (const float*)d_in[3];
    const float* hs = (const float*)d_in[4];
    float* out = (float*)d_out;

    int B = in_sizes[0] / 1024;          // 8192
    const int smem_bytes = 65536 + 32768 + 1024;

    precompute_tables<<<1, 256>>>(ae, ad);

    cudaFuncSetAttribute(enc_dec_kernel,
                         cudaFuncAttributeMaxDynamicSharedMemorySize, smem_bytes);
    int blocks = B / 16;                 // 16 rows per block (16 warps x 1 row)
    enc_dec_kernel<<<blocks, 512, smem_bytes>>>(x, hw, hs, out, B);
}